// round 3
// baseline (speedup 1.0000x reference)
#include <cuda_runtime.h>

// Problem constants
#define NCTA   128
#define TPB    512
#define NB     512
#define BT     4       // batch elements per CTA
#define NC     184     // cities
#define HH     32      // hidden
#define IND    14      // in_dim
#define DD     15      // in_dim + 1
#define NPRED  24
#define NHIST  24
#define NFEAT  13      // in_dim - 1
#define FTOT   48      // hist + pred

// Global scratch (per-CTA private slices; same-CTA produce/consume only)
__device__ float g_y0[(size_t)NCTA * NC * BT * 64];

// Shared memory layout (float offsets)
#define OFF_X    0        // 184*15*4 = 11040   x tile [c][k][b]
#define OFF_XIN  11040    // 2*2*256  = 1024    L1 staged input [dir][buf][k*4+b]
#define OFF_GP   12064    // 2*2*4*128= 2048    gate partials [dir][half][b][row]
#define OFF_H    14112    // 4*32*4   = 512     h state [ld][k][b]
#define OFF_C    14624    // 4*32*4   = 512     c state [ld][k][b]
#define OFF_XN   15136    // 184*4    = 736     xn [c][b]
#define OFF_GX   15872    // 4*96     = 384
#define OFF_GH   16256    // 16*96    = 1536
#define OFF_U    17792    // 4*16     = 64
#define OFF_MP   17856    // 2*184*4  = 1472    MLP partials
#define SMEM_FLOATS 19328 // 77,312 bytes

typedef unsigned long long u64;

__device__ __forceinline__ u64 pk2(float w) {
    u64 r;
    asm("mov.b64 %0, {%1, %1};" : "=l"(r) : "f"(w));
    return r;
}
__device__ __forceinline__ void ffma2(u64& a, u64 x, u64 w) {
    asm("fma.rn.f32x2 %0, %1, %2, %0;" : "+l"(a) : "l"(x), "l"(w));
}
__device__ __forceinline__ float2 unpk(u64 a) {
    float2 f;
    asm("mov.b64 {%0, %1}, %2;" : "=f"(f.x), "=f"(f.y) : "l"(a));
    return f;
}
__device__ __forceinline__ float sigf(float x) {
    return __fdividef(1.0f, 1.0f + __expf(-x));
}
__device__ __forceinline__ float tanhfast(float x) {
    x = fminf(fmaxf(x, -15.0f), 15.0f);
    float e = __expf(2.0f * x);
    return __fdividef(e - 1.0f, e + 1.0f);
}
__device__ __forceinline__ void dbar(int dir) {
    asm volatile("bar.sync %0, %1;" :: "r"(1 + dir), "r"(256) : "memory");
}

__global__ void __launch_bounds__(TPB, 1)
bilstm_kernel(const float* __restrict__ rain_hist,
              const float* __restrict__ feature,
              const float* __restrict__ h0,
              const float* __restrict__ c0,
              const float* __restrict__ W_mlp,
              const float* __restrict__ b_mlp,
              const float* __restrict__ Wih_g,
              const float* __restrict__ Whh_g,
              const float* __restrict__ b_ih_g,
              const float* __restrict__ b_hh_g,
              const float* __restrict__ Wih0,
              const float* __restrict__ Whh0,
              const float* __restrict__ b0,
              const float* __restrict__ Wih1,
              const float* __restrict__ Whh1,
              const float* __restrict__ b1,
              const float* __restrict__ W_fc,
              const float* __restrict__ b_fc,
              float* __restrict__ out)
{
    extern __shared__ float sm[];
    float* sX   = sm + OFF_X;
    float* sXin = sm + OFF_XIN;
    float* sGP  = sm + OFF_GP;
    float* sH   = sm + OFF_H;
    float* sCst = sm + OFF_C;
    float* sXN  = sm + OFF_XN;
    float* sGX  = sm + OFF_GX;
    float* sGH  = sm + OFF_GH;
    float* sU   = sm + OFF_U;
    float* sMP  = sm + OFF_MP;

    const int tid  = threadIdx.x;
    const int cta  = blockIdx.x;
    const int bg   = cta * BT;
    const int lane = tid & 31;
    const int wid  = tid >> 5;          // 0..15
    const int dir  = wid >> 3;          // 0/1 (warps 0-7 dir0, 8-15 dir1)
    const int w8   = wid & 7;           // 0..7 within dir domain
    const int half = w8 >> 2;           // k-half
    const int rowg = w8 & 3;
    const int row  = rowg * 32 + lane;  // gate row within dir (0..127)
    const int et   = w8 * 32 + lane;    // 0..255 within dir domain
    const int bup  = w8;                // update-phase batch (w8<4 only)
    const int ju   = lane;

    // ---- per-thread weight half-rows in registers ----
    float w0[24], w1[48], bias0, bias1;
    {
        const int gr = dir * 128 + row;
        if (half == 0) {
#pragma unroll
            for (int i = 0; i < 15; ++i) w0[i] = Wih0[gr * DD + i];
#pragma unroll
            for (int i = 0; i < 9; ++i)  w0[15 + i] = Whh0[gr * HH + i];
            bias0 = b0[gr];
#pragma unroll
            for (int i = 0; i < 48; ++i) w1[i] = Wih1[gr * 64 + i];
            bias1 = b1[gr];
        } else {
#pragma unroll
            for (int i = 0; i < 23; ++i) w0[i] = Whh0[gr * HH + 9 + i];
            w0[23] = 0.0f;
            bias0 = 0.0f;
#pragma unroll
            for (int i = 0; i < 16; ++i) w1[i] = Wih1[gr * 64 + 48 + i];
#pragma unroll
            for (int i = 0; i < 32; ++i) w1[16 + i] = Whh1[gr * HH + i];
            bias1 = 0.0f;
        }
    }
    const float wfc = W_fc[lane];
    const float bfc = b_fc[0];

    // ---- initial states ----
    for (int e = tid; e < 4 * HH * BT; e += TPB) {
        int ld = e >> 7, k = (e >> 2) & 31, b = e & 3;
        sH[(ld * HH + k) * BT + b]   = h0[((size_t)ld * NB + bg + b) * HH + k];
        sCst[(ld * HH + k) * BT + b] = c0[((size_t)ld * NB + bg + b) * HH + k];
    }
    for (int e = tid; e < NC * BT; e += TPB) {
        int c = e >> 2, b = e & 3;
        sXN[c * BT + b] = rain_hist[((size_t)(bg + b) * NHIST + (NHIST - 1)) * NC + c];
    }
    __syncthreads();

    for (int t = 0; t < NPRED; ++t) {
        // ============ Phase 1: build x tile ============
        for (int e = tid; e < NC * NFEAT * BT; e += TPB) {
            int b = e / (NC * NFEAT);
            int rem = e - b * (NC * NFEAT);
            int c = rem / NFEAT;
            int kk = rem - c * NFEAT;
            sX[(c * DD + 2 + kk) * BT + b] =
                feature[(((size_t)(bg + b) * FTOT + NHIST + t) * NC + c) * NFEAT + kk];
        }
        for (int e = tid; e < NC * BT; e += TPB) {
            int c = e >> 2, b = e & 3;
            sX[(c * DD + 1) * BT + b] = sXN[c * BT + b];
        }
        __syncthreads();

        // ============ Phase 2: gated graph MLP (c-split in halves) ============
        if (tid < 368) {
            const int j = tid >> 1, ch = tid & 1;
            u64 a01 = (ch == 0) ? pk2(b_mlp[j]) : pk2(0.0f);
            u64 a23 = a01;
            const float* wbase = W_mlp + j;
            for (int c = ch * 92; c < ch * 92 + 92; ++c) {
                const ulonglong2* xp = (const ulonglong2*)(sX + (c * DD + 1) * BT);
                const float* wp = wbase + (size_t)c * IND * NC;
#pragma unroll
                for (int kk = 0; kk < IND; ++kk) {
                    u64 w = pk2(wp[(size_t)kk * NC]);
                    ulonglong2 xv = xp[kk];
                    ffma2(a01, xv.x, w);
                    ffma2(a23, xv.y, w);
                }
            }
            float2 v01 = unpk(a01), v23 = unpk(a23);
            float4* mp = (float4*)(sMP + (ch * NC + j) * 4);
            *mp = make_float4(v01.x, v01.y, v23.x, v23.y);
        }
        __syncthreads();
        if (tid < NC) {
            const int j = tid;
#pragma unroll
            for (int b = 0; b < 4; ++b) {
                float a = sMP[j * 4 + b] + sMP[(NC + j) * 4 + b];
                sX[(j * DD) * BT + b] = sigf(a);
            }
        }
        __syncthreads();

        // ============ Phase 3: GRU cell ============
        for (int e = tid; e < BT * DD; e += TPB) {
            int b = e / DD, k = e - b * DD;
            float s = 0.0f;
            for (int c = 0; c < NC; ++c) s += sX[(c * DD + k) * BT + b];
            sU[b * 16 + k] = s * (1.0f / NC);
        }
        __syncthreads();
        for (int e = tid; e < BT * 96; e += TPB) {
            int b = e / 96, j = e - b * 96;
            float a = b_ih_g[j];
#pragma unroll
            for (int k = 0; k < DD; ++k)
                a = fmaf(sU[b * 16 + k], Wih_g[k * 96 + j], a);
            sGX[e] = a;
        }
        for (int e = tid; e < 16 * 96; e += TPB) {
            int lb = e / 96, j = e - lb * 96;
            int l = lb >> 2, b = lb & 3;
            float a = b_hh_g[j];
#pragma unroll
            for (int k = 0; k < HH; ++k)
                a = fmaf(sH[(l * HH + k) * BT + b], Whh_g[k * 96 + j], a);
            sGH[e] = a;
        }
        __syncthreads();
        for (int e = tid; e < 4 * BT * HH; e += TPB) {
            int l = e >> 7, b = (e >> 5) & 3, j = e & 31;
            int gb = b * 96, ghb = (l * BT + b) * 96;
            float r = sigf(sGX[gb + j]      + sGH[ghb + j]);
            float z = sigf(sGX[gb + 32 + j] + sGH[ghb + 32 + j]);
            float n = tanhfast(sGX[gb + 64 + j] + r * sGH[ghb + 64 + j]);
            int hi = (l * HH + j) * BT + b;
            sH[hi] = (1.0f - z) * n + z * sH[hi];
        }
        __syncthreads();

        // ============ Phase 4: BiLSTM layer 0 (dir-split barrier domains) ============
        {
            const ulonglong2* hp = (const ulonglong2*)(sH + dir * HH * BT);
            float* gpw = sGP + ((dir * 2 + half) * 4) * 128 + row;
            const float* gpr0 = sGP + ((dir * 2 + 0) * 4 + bup) * 128;
            const float* gpr1 = sGP + ((dir * 2 + 1) * 4 + bup) * 128;
            for (int s = 0; s < NC; ++s) {
                const int city = dir ? (NC - 1 - s) : s;
                u64 a01 = pk2(bias0), a23 = a01;
                if (half == 0) {
                    const ulonglong2* xp = (const ulonglong2*)(sX + city * DD * BT);
#pragma unroll
                    for (int k = 0; k < DD; ++k) {
                        u64 w = pk2(w0[k]);
                        ulonglong2 xv = xp[k];
                        ffma2(a01, xv.x, w); ffma2(a23, xv.y, w);
                    }
#pragma unroll
                    for (int k = 0; k < 9; ++k) {
                        u64 w = pk2(w0[15 + k]);
                        ulonglong2 hv = hp[k];
                        ffma2(a01, hv.x, w); ffma2(a23, hv.y, w);
                    }
                } else {
#pragma unroll
                    for (int k = 0; k < 23; ++k) {
                        u64 w = pk2(w0[k]);
                        ulonglong2 hv = hp[9 + k];
                        ffma2(a01, hv.x, w); ffma2(a23, hv.y, w);
                    }
                }
                float2 v01 = unpk(a01), v23 = unpk(a23);
                gpw[0] = v01.x; gpw[128] = v01.y; gpw[256] = v23.x; gpw[384] = v23.y;
                dbar(dir);
                if (w8 < 4) {
                    float p0 = gpr0[ju]       + gpr1[ju];
                    float p1 = gpr0[32 + ju]  + gpr1[32 + ju];
                    float p2 = gpr0[64 + ju]  + gpr1[64 + ju];
                    float p3 = gpr0[96 + ju]  + gpr1[96 + ju];
                    float iv = sigf(p0), fv = sigf(p1);
                    float gv = tanhfast(p2), ov = sigf(p3);
                    int ci = (dir * HH + ju) * BT + bup;
                    float cc = fmaf(fv, sCst[ci], iv * gv);
                    sCst[ci] = cc;
                    float hh2 = ov * tanhfast(cc);
                    sH[ci] = hh2;
                    g_y0[((size_t)(cta * NC + city) * BT + bup) * 64 + dir * 32 + ju] = hh2;
                }
                dbar(dir);
            }
        }
        __syncthreads();  // both dirs' y0 complete before L1 staging

        // ============ Phase 5: BiLSTM layer 1 (prefetch + dbl buffer, dir-split) ============
        {
            // stage s=0 into buffer 0 (per dir domain)
            {
                int k = et >> 2, b = et & 3;
                int city0 = dir ? (NC - 1) : 0;
                sXin[(dir * 2 + 0) * 256 + et] =
                    g_y0[((size_t)(cta * NC + city0) * BT + b) * 64 + k];
            }
            dbar(dir);
            int buf = 0;
            const ulonglong2* hp = (const ulonglong2*)(sH + (2 + dir) * HH * BT);
            float* gpw = sGP + ((dir * 2 + half) * 4) * 128 + row;
            const float* gpr0 = sGP + ((dir * 2 + 0) * 4 + bup) * 128;
            const float* gpr1 = sGP + ((dir * 2 + 1) * 4 + bup) * 128;
            const int kst = et >> 2, bst = et & 3;
            for (int s = 0; s < NC; ++s) {
                // prefetch next city's input
                const int sp = (s + 1 < NC) ? (s + 1) : s;
                const int cityp = dir ? (NC - 1 - sp) : sp;
                float pf = g_y0[((size_t)(cta * NC + cityp) * BT + bst) * 64 + kst];
                // gates
                const ulonglong2* xp = (const ulonglong2*)(sXin + (dir * 2 + buf) * 256);
                u64 a01 = pk2(bias1), a23 = a01;
                if (half == 0) {
#pragma unroll
                    for (int k = 0; k < 48; ++k) {
                        u64 w = pk2(w1[k]);
                        ulonglong2 xv = xp[k];
                        ffma2(a01, xv.x, w); ffma2(a23, xv.y, w);
                    }
                } else {
#pragma unroll
                    for (int k = 0; k < 16; ++k) {
                        u64 w = pk2(w1[k]);
                        ulonglong2 xv = xp[48 + k];
                        ffma2(a01, xv.x, w); ffma2(a23, xv.y, w);
                    }
#pragma unroll
                    for (int k = 0; k < 32; ++k) {
                        u64 w = pk2(w1[16 + k]);
                        ulonglong2 hv = hp[k];
                        ffma2(a01, hv.x, w); ffma2(a23, hv.y, w);
                    }
                }
                float2 v01 = unpk(a01), v23 = unpk(a23);
                gpw[0] = v01.x; gpw[128] = v01.y; gpw[256] = v23.x; gpw[384] = v23.y;
                dbar(dir);
                // stash prefetched input into other buffer
                sXin[(dir * 2 + (buf ^ 1)) * 256 + et] = pf;
                if (w8 < 4) {
                    float p0 = gpr0[ju]       + gpr1[ju];
                    float p1 = gpr0[32 + ju]  + gpr1[32 + ju];
                    float p2 = gpr0[64 + ju]  + gpr1[64 + ju];
                    float p3 = gpr0[96 + ju]  + gpr1[96 + ju];
                    float iv = sigf(p0), fv = sigf(p1);
                    float gv = tanhfast(p2), ov = sigf(p3);
                    int ci = ((2 + dir) * HH + ju) * BT + bup;
                    float cc = fmaf(fv, sCst[ci], iv * gv);
                    sCst[ci] = cc;
                    float hh2 = ov * tanhfast(cc);
                    sH[ci] = hh2;
                    if (dir == 0) {
                        // inline FC head: xn[s][b] = sum_j W_fc[j]*hh2 + b_fc
                        float v = wfc * hh2;
                        v += __shfl_xor_sync(0xffffffffu, v, 16);
                        v += __shfl_xor_sync(0xffffffffu, v, 8);
                        v += __shfl_xor_sync(0xffffffffu, v, 4);
                        v += __shfl_xor_sync(0xffffffffu, v, 2);
                        v += __shfl_xor_sync(0xffffffffu, v, 1);
                        if (ju == 0) {
                            float a = v + bfc;
                            sXN[s * BT + bup] = a;
                            out[((size_t)(bg + bup) * NPRED + t) * NC + s] = a;
                        }
                    }
                }
                dbar(dir);
                buf ^= 1;
            }
        }
        __syncthreads();
    }
}

extern "C" void kernel_launch(void* const* d_in, const int* in_sizes, int n_in,
                              void* d_out, int out_size) {
    (void)in_sizes; (void)n_in; (void)out_size;
    const float* rain_hist = (const float*)d_in[0];
    const float* feature   = (const float*)d_in[1];
    const float* h0        = (const float*)d_in[2];
    const float* c0        = (const float*)d_in[3];
    const float* W_mlp     = (const float*)d_in[4];
    const float* b_mlp     = (const float*)d_in[5];
    const float* Wih_g     = (const float*)d_in[6];
    const float* Whh_g     = (const float*)d_in[7];
    const float* b_ih_g    = (const float*)d_in[8];
    const float* b_hh_g    = (const float*)d_in[9];
    const float* Wih0      = (const float*)d_in[10];
    const float* Whh0      = (const float*)d_in[11];
    const float* b0        = (const float*)d_in[12];
    const float* Wih1      = (const float*)d_in[13];
    const float* Whh1      = (const float*)d_in[14];
    const float* b1        = (const float*)d_in[15];
    const float* W_fc      = (const float*)d_in[16];
    const float* b_fc      = (const float*)d_in[17];

    size_t smem = (size_t)SMEM_FLOATS * sizeof(float);
    cudaFuncSetAttribute(bilstm_kernel,
                         cudaFuncAttributeMaxDynamicSharedMemorySize, (int)smem);

    bilstm_kernel<<<NCTA, TPB, smem>>>(
        rain_hist, feature, h0, c0, W_mlp, b_mlp,
        Wih_g, Whh_g, b_ih_g, b_hh_g,
        Wih0, Whh0, b0, Wih1, Whh1, b1,
        W_fc, b_fc, (float*)d_out);
}